// round 8
// baseline (speedup 1.0000x reference)
#include <cuda_runtime.h>
#include <math.h>

#define BB 2
#define DD 64
#define HH 96
#define WW 96
#define VOL (DD*HH*WW)          // 589824
#define NVOX (BB*VOL)           // 1179648
#define HWSZ (HH*WW)            // 9216
#define NPLANE (BB*DD)          // 128
#define BIGF 1e10f
#define WT 32                   // passBC w-tile
#define WT3 16                  // pass3 w-tile

#define NBLK3 (BB*HH*(WW/WT3))  // 1152 pass3 blocks

// Scratch (device globals: allocation-free per harness rules)
__device__ float2 g_f2[NVOX];             // {fpos, fneg} after W+H transform
__device__ volatile float g_pn[NBLK3];
__device__ volatile float g_pd[NBLK3];
__device__ unsigned g_count;              // zero-init; last block resets -> deterministic

// Distance (voxels) from w (0..95) to nearest set bit of the 96-bit row mask
// {lo: bits 0-63, hi: bits 64-95}. Returns huge if none.
__device__ __forceinline__ int nearest_bit(unsigned long long lo, unsigned hi, int w) {
    const int INF = 1 << 30;
    int up = INF, down = INF;
    if (w < 64) {
        unsigned long long a = lo >> w;
        if (a) up = __ffsll((long long)a) - 1;
        else if (hi) up = (64 - w) + (__ffs((int)hi) - 1);
        unsigned long long b = lo << (63 - w);
        if (b) down = __clzll((long long)b);
    } else {
        int w2 = w - 64;
        unsigned a = hi >> w2;
        if (a) up = __ffs((int)a) - 1;
        unsigned b = hi << (31 - w2);
        if (b) down = __clz((int)b);
        else if (lo) down = (w2 + 1) + __clzll((long long)lo);
    }
    return (up < down) ? up : down;
}

// Fused: mask build (ballot) + pass1 (bit-scan along W, both phases)
// + pass2 (early-exit scan along H in smem). Block = (plane, w-tile).
__global__ __launch_bounds__(256) void k_passBC(const float* __restrict__ tgt) {
    __shared__ unsigned smask[HH][3];
    __shared__ float s1p[HH][WT];
    __shared__ float s1n[HH][WT];

    int wt = blockIdx.x % 3;
    int bd = blockIdx.x / 3;
    int base = bd * HWSZ;
    int tid = threadIdx.x;
    int lane = tid & 31;
    int warp = tid >> 5;              // 0..7

    // Build this plane's row masks: 288 warp-tasks over 8 warps.
    #pragma unroll 4
    for (int task = warp; task < HH * 3; task += 8) {
        int h = task / 3, seg = task % 3;
        float v = tgt[base + h * WW + seg * 32 + lane];
        unsigned m = __ballot_sync(0xFFFFFFFFu, v > 0.5f);
        if (lane == 0) smask[h][seg] = m;
    }
    __syncthreads();

    // pass1: exact distance along W via bit scan; both phases.
    #pragma unroll 1
    for (int v = tid; v < HH * WT; v += 256) {
        int h = v >> 5;
        int wl = v & 31;
        int w = wt * WT + wl;
        unsigned long long lo = (unsigned long long)smask[h][0]
                              | ((unsigned long long)smask[h][1] << 32);
        unsigned hi = smask[h][2];
        int dn = nearest_bit(lo, hi, w);        // nearest 1
        int dp = nearest_bit(~lo, ~hi, w);      // nearest 0
        s1p[h][wl] = (dp > 95) ? BIGF : (float)(dp * dp);
        s1n[h][wl] = (dn > 95) ? BIGF : (float)(dn * dn);
    }
    __syncthreads();

    // pass2 along H: k=1..3 unconditional (fmin no-op wherever old early exit
    // fired, since f>=0 -> exact), then early-exit loop.
    #pragma unroll 1
    for (int v = tid; v < HH * WT; v += 256) {
        int i = v >> 5;
        int wl = v & 31;
        float bp = s1p[i][wl];
        float bn = s1n[i][wl];
        #pragma unroll
        for (int k = 1; k <= 3; ++k) {
            float k2 = (float)(k * k);
            int lo_ = i - k, hi_ = i + k;
            if (lo_ >= 0) {
                bp = fminf(bp, s1p[lo_][wl] + k2);
                bn = fminf(bn, s1n[lo_][wl] + k2);
            }
            if (hi_ < HH) {
                bp = fminf(bp, s1p[hi_][wl] + k2);
                bn = fminf(bn, s1n[hi_][wl] + k2);
            }
        }
        #pragma unroll 1
        for (int k = 4; k < HH; ++k) {
            float k2 = (float)(k * k);
            if (k2 >= bp && k2 >= bn) break;
            int lo_ = i - k, hi_ = i + k;
            if (lo_ >= 0) {
                bp = fminf(bp, s1p[lo_][wl] + k2);
                bn = fminf(bn, s1n[lo_][wl] + k2);
            }
            if (hi_ < HH) {
                bp = fminf(bp, s1p[hi_][wl] + k2);
                bn = fminf(bn, s1n[hi_][wl] + k2);
            }
        }
        g_f2[base + i * WW + wt * WT + wl] = make_float2(bp, bn);
    }
}

// Pass3: along D in smem, fused loss epilogue + grid-final reduction.
// WT3=16 -> 1152 blocks for wave balance. No tgt read (t == (bp>0)).
__global__ __launch_bounds__(256) void k_pass3(const float* __restrict__ pred,
                                               float* __restrict__ out) {
    __shared__ float sfp[DD][WT3];
    __shared__ float sfn[DD][WT3];
    __shared__ float rn[8], rd[8];
    __shared__ int s_last;

    int wt = blockIdx.x % (WW / WT3);       // 0..5
    int bh = blockIdx.x / (WW / WT3);
    int b = bh / HH;
    int h = bh % HH;
    int base = b * VOL + h * WW + wt * WT3;
    int tid = threadIdx.x;

    #pragma unroll
    for (int r = tid; r < DD * WT3; r += 256) {
        int d = r >> 4, w = r & 15;
        float2 v = g_f2[base + d * HWSZ + w];
        sfp[d][w] = v.x;
        sfn[d][w] = v.y;
    }
    __syncthreads();

    int w = tid & 15;
    int c0 = tid >> 4;  // 0..15
    float accn = 0.0f, accd = 0.0f;

    #pragma unroll 1
    for (int i = c0; i < DD; i += 16) {
        float bp = sfp[i][w];
        float bn = sfn[i][w];
        #pragma unroll
        for (int k = 1; k <= 3; ++k) {
            float k2 = (float)(k * k);
            int lo = i - k, hi = i + k;
            if (lo >= 0) {
                bp = fminf(bp, sfp[lo][w] + k2);
                bn = fminf(bn, sfn[lo][w] + k2);
            }
            if (hi < DD) {
                bp = fminf(bp, sfp[hi][w] + k2);
                bn = fminf(bn, sfn[hi][w] + k2);
            }
        }
        #pragma unroll 1
        for (int k = 4; k < DD; ++k) {
            float k2 = (float)(k * k);
            if (k2 >= bp && k2 >= bn) break;
            int lo = i - k, hi = i + k;
            if (lo >= 0) {
                bp = fminf(bp, sfp[lo][w] + k2);
                bn = fminf(bn, sfn[lo][w] + k2);
            }
            if (hi < DD) {
                bp = fminf(bp, sfp[hi][w] + k2);
                bn = fminf(bn, sfn[hi][w] + k2);
            }
        }
        // Exactly one of bp,bn is 0: a = sqrt(max(bp,bn)); sqrt only in (3,5) band.
        float m = fmaxf(bp, bn);
        float wgt;
        if (m <= 9.0f)       wgt = 1.0f;
        else if (m >= 25.0f) wgt = 0.0f;
        else                 wgt = 1.0f - (sqrtf(m) - 3.0f) * 0.5f;

        // t==1 <=> bn==0 <=> bp>0, exactly. bce = -clamp(log(t?p:1-p), -100).
        float p = pred[base + i * HWSZ + w];
        float pc = (bp > 0.0f) ? p : (1.0f - p);
        float bce = -fmaxf(__logf(pc), -100.0f);
        accn += bce * wgt;
        accd += wgt;
    }

    #pragma unroll
    for (int off = 16; off > 0; off >>= 1) {
        accn += __shfl_down_sync(0xFFFFFFFFu, accn, off);
        accd += __shfl_down_sync(0xFFFFFFFFu, accd, off);
    }
    int warp = tid >> 5, lane = tid & 31;
    if (lane == 0) { rn[warp] = accn; rd[warp] = accd; }
    __syncthreads();
    if (tid == 0) {
        float sn = 0.0f, sd = 0.0f;
        #pragma unroll
        for (int j = 0; j < 8; ++j) { sn += rn[j]; sd += rd[j]; }
        g_pn[blockIdx.x] = sn;
        g_pd[blockIdx.x] = sd;
        __threadfence();
        unsigned old = atomicAdd(&g_count, 1u);
        s_last = (old == NBLK3 - 1) ? 1 : 0;
    }
    __syncthreads();

    // Last block: reduce all 1152 partials -> scalar, reset counter.
    if (s_last) {
        __shared__ double wn[8], wd[8];
        const int PER_B = NBLK3 / BB;     // 576
        int rb = tid >> 7;                // 0..1 (batch)
        int j0 = tid & 127;
        double an = 0.0, ad = 0.0;
        #pragma unroll
        for (int j = j0; j < PER_B; j += 128) {
            an += (double)g_pn[rb * PER_B + j];
            ad += (double)g_pd[rb * PER_B + j];
        }
        #pragma unroll
        for (int off = 16; off > 0; off >>= 1) {
            an += __shfl_down_sync(0xFFFFFFFFu, an, off);
            ad += __shfl_down_sync(0xFFFFFFFFu, ad, off);
        }
        if (lane == 0) { wn[warp] = an; wd[warp] = ad; }
        __syncthreads();
        if (tid == 0) {
            double n0 = 0.0, dd0 = 0.0, n1 = 0.0, dd1 = 0.0;
            #pragma unroll
            for (int j = 0; j < 4; ++j) { n0 += wn[j]; dd0 += wd[j]; }
            #pragma unroll
            for (int j = 4; j < 8; ++j) { n1 += wn[j]; dd1 += wd[j]; }
            double acc = n0 / (dd0 + 1e-5) + n1 / (dd1 + 1e-5);
            out[0] = (float)(acc / (double)BB);
            g_count = 0;   // reset for next graph replay
        }
    }
}

extern "C" void kernel_launch(void* const* d_in, const int* in_sizes, int n_in,
                              void* d_out, int out_size) {
    const float* pred = (const float*)d_in[0];
    const float* tgt  = (const float*)d_in[1];
    (void)in_sizes; (void)n_in; (void)out_size;

    k_passBC<<<NPLANE * 3, 256>>>(tgt);             // 384 blocks
    k_pass3<<<NBLK3, 256>>>(pred, (float*)d_out);   // 1152 blocks
}

// round 9
// speedup vs baseline: 1.0094x; 1.0094x over previous
#include <cuda_runtime.h>
#include <math.h>

#define BB 2
#define DD 64
#define HH 96
#define WW 96
#define VOL (DD*HH*WW)          // 589824
#define NVOX (BB*VOL)           // 1179648
#define HWSZ (HH*WW)            // 9216
#define NPLANE (BB*DD)          // 128
#define WT 32                   // passBC w-tile
#define WT3 16                  // pass3 w-tile
#define CLAMP 25.0f

#define NBLK3 (BB*HH*(WW/WT3))  // 1152 pass3 blocks

// Scratch (device globals: allocation-free per harness rules)
__device__ float g_x[NVOX];               // packed bp-bn after W+H transform (clamped 25)
__device__ volatile float g_pn[NBLK3];
__device__ volatile float g_pd[NBLK3];
__device__ unsigned g_count;              // zero-init; last block resets -> deterministic

// Distance (voxels) from w (0..95) to nearest set bit of the 96-bit row mask.
__device__ __forceinline__ int nearest_bit(unsigned long long lo, unsigned hi, int w) {
    const int INF = 1 << 30;
    int up = INF, down = INF;
    if (w < 64) {
        unsigned long long a = lo >> w;
        if (a) up = __ffsll((long long)a) - 1;
        else if (hi) up = (64 - w) + (__ffs((int)hi) - 1);
        unsigned long long b = lo << (63 - w);
        if (b) down = __clzll((long long)b);
    } else {
        int w2 = w - 64;
        unsigned a = hi >> w2;
        if (a) up = __ffs((int)a) - 1;
        unsigned b = hi << (31 - w2);
        if (b) down = __clz((int)b);
        else if (lo) down = (w2 + 1) + __clzll((long long)lo);
    }
    return (up < down) ? up : down;
}

// Fused: mask build (ballot) + pass1 (bit-scan along W, clamped at 25)
// + pass2 (branch-free k=1..4 stencil along H in padded smem).
__global__ __launch_bounds__(256) void k_passBC(const float* __restrict__ tgt) {
    __shared__ unsigned smask[HH][3];
    __shared__ float s1p[HH + 8][WT];
    __shared__ float s1n[HH + 8][WT];

    int wt = blockIdx.x % 3;
    int bd = blockIdx.x / 3;
    int base = bd * HWSZ;
    int tid = threadIdx.x;
    int lane = tid & 31;
    int warp = tid >> 5;              // 0..7

    // Build this plane's row masks: 288 warp-tasks over 8 warps.
    #pragma unroll 4
    for (int task = warp; task < HH * 3; task += 8) {
        int h = task / 3, seg = task % 3;
        float v = tgt[base + h * WW + seg * 32 + lane];
        unsigned m = __ballot_sync(0xFFFFFFFFu, v > 0.5f);
        if (lane == 0) smask[h][seg] = m;
    }
    // Pad rows [0..3] and [HH+4..HH+7] with the clamp value (never wins a min).
    {
        int r = tid >> 5;             // 0..7
        int w = tid & 31;
        int row = (r < 4) ? r : (HH + r);
        s1p[row][w] = CLAMP;
        s1n[row][w] = CLAMP;
    }
    __syncthreads();

    // pass1: exact distance along W via bit scan; clamp at 25 (d>=5 -> 25).
    #pragma unroll 1
    for (int v = tid; v < HH * WT; v += 256) {
        int h = v >> 5;
        int wl = v & 31;
        int w = wt * WT + wl;
        unsigned long long lo = (unsigned long long)smask[h][0]
                              | ((unsigned long long)smask[h][1] << 32);
        unsigned hi = smask[h][2];
        int dn = nearest_bit(lo, hi, w);        // nearest 1
        int dp = nearest_bit(~lo, ~hi, w);      // nearest 0
        s1p[4 + h][wl] = (dp >= 5) ? CLAMP : (float)(dp * dp);
        s1n[4 + h][wl] = (dn >= 5) ? CLAMP : (float)(dn * dn);
    }
    __syncthreads();

    // pass2 along H: fixed k=1..4 stencil, no branches (k=5 -> k^2=25 >= clamp).
    #pragma unroll 1
    for (int v = tid; v < HH * WT; v += 256) {
        int i = v >> 5;
        int wl = v & 31;
        int ii = i + 4;
        float bp = s1p[ii][wl];
        float bn = s1n[ii][wl];
        #pragma unroll
        for (int k = 1; k <= 4; ++k) {
            float k2 = (float)(k * k);
            bp = fminf(bp, s1p[ii - k][wl] + k2);
            bp = fminf(bp, s1p[ii + k][wl] + k2);
            bn = fminf(bn, s1n[ii - k][wl] + k2);
            bn = fminf(bn, s1n[ii + k][wl] + k2);
        }
        // Exactly one of bp,bn is 0 -> pack as signed value.
        g_x[base + i * WW + wt * WT + wl] = bp - bn;
    }
}

// Pass3: branch-free k=1..4 stencil along D in padded smem, fused loss
// epilogue (group-4 log) + grid-final reduction.
__global__ __launch_bounds__(256) void k_pass3(const float* __restrict__ pred,
                                               float* __restrict__ out) {
    __shared__ float sfp[DD + 8][WT3];
    __shared__ float sfn[DD + 8][WT3];
    __shared__ float rn[8], rd[8];
    __shared__ int s_last;

    int wt = blockIdx.x % (WW / WT3);       // 0..5
    int bh = blockIdx.x / (WW / WT3);
    int b = bh / HH;
    int h = bh % HH;
    int base = b * VOL + h * WW + wt * WT3;
    int tid = threadIdx.x;

    // Pad rows [0..3] and [DD+4..DD+7].
    if (tid < 128) {
        int r = tid >> 4;             // 0..7
        int w = tid & 15;
        int row = (r < 4) ? r : (DD + r);
        sfp[row][w] = CLAMP;
        sfn[row][w] = CLAMP;
    }
    // Load + decode packed values.
    #pragma unroll
    for (int r = tid; r < DD * WT3; r += 256) {
        int d = r >> 4, w = r & 15;
        float x = g_x[base + d * HWSZ + w];
        sfp[4 + d][w] = fmaxf(x, 0.0f);
        sfn[4 + d][w] = fmaxf(-x, 0.0f);
    }
    __syncthreads();

    int w = tid & 15;
    int c0 = tid >> 4;  // 0..15
    float mArr[4], pcArr[4];

    #pragma unroll
    for (int j = 0; j < 4; ++j) {
        int i = c0 + 16 * j;
        float p = pred[base + i * HWSZ + w];   // issue LDG early
        int ii = i + 4;
        float bp = sfp[ii][w];
        float bn = sfn[ii][w];
        #pragma unroll
        for (int k = 1; k <= 4; ++k) {
            float k2 = (float)(k * k);
            bp = fminf(bp, sfp[ii - k][w] + k2);
            bp = fminf(bp, sfp[ii + k][w] + k2);
            bn = fminf(bn, sfn[ii - k][w] + k2);
            bn = fminf(bn, sfn[ii + k][w] + k2);
        }
        mArr[j] = fmaxf(bp, bn);               // exactly one is 0
        pcArr[j] = (bp > 0.0f) ? p : (1.0f - p);  // t==1 <=> bp>0
    }

    float accn, accd;
    bool fast = true;
    float prod = 1.0f;
    #pragma unroll
    for (int j = 0; j < 4; ++j) {
        if (mArr[j] > 9.0f) fast = false;
        prod *= pcArr[j];
    }
    if (fast && prod > 1e-30f) {
        // all w==1, no clamps can trigger: sum(-log pc) == -log(prod)
        accn = -__logf(prod);
        accd = 4.0f;
    } else {
        accn = 0.0f; accd = 0.0f;
        #pragma unroll
        for (int j = 0; j < 4; ++j) {
            float m = mArr[j];
            float wgt;
            if (m <= 9.0f)       wgt = 1.0f;
            else if (m >= 25.0f) wgt = 0.0f;
            else                 wgt = 1.0f - (sqrtf(m) - 3.0f) * 0.5f;
            float bce = -fmaxf(__logf(pcArr[j]), -100.0f);
            accn += bce * wgt;
            accd += wgt;
        }
    }

    #pragma unroll
    for (int off = 16; off > 0; off >>= 1) {
        accn += __shfl_down_sync(0xFFFFFFFFu, accn, off);
        accd += __shfl_down_sync(0xFFFFFFFFu, accd, off);
    }
    int warp = tid >> 5, lane = tid & 31;
    if (lane == 0) { rn[warp] = accn; rd[warp] = accd; }
    __syncthreads();
    if (tid == 0) {
        float sn = 0.0f, sd = 0.0f;
        #pragma unroll
        for (int j = 0; j < 8; ++j) { sn += rn[j]; sd += rd[j]; }
        g_pn[blockIdx.x] = sn;
        g_pd[blockIdx.x] = sd;
        __threadfence();
        unsigned old = atomicAdd(&g_count, 1u);
        s_last = (old == NBLK3 - 1) ? 1 : 0;
    }
    __syncthreads();

    // Last block: reduce all 1152 partials -> scalar, reset counter.
    if (s_last) {
        __shared__ double wn[8], wd[8];
        const int PER_B = NBLK3 / BB;     // 576
        int rb = tid >> 7;                // 0..1 (batch)
        int j0 = tid & 127;
        double an = 0.0, ad = 0.0;
        #pragma unroll
        for (int j = j0; j < PER_B; j += 128) {
            an += (double)g_pn[rb * PER_B + j];
            ad += (double)g_pd[rb * PER_B + j];
        }
        #pragma unroll
        for (int off = 16; off > 0; off >>= 1) {
            an += __shfl_down_sync(0xFFFFFFFFu, an, off);
            ad += __shfl_down_sync(0xFFFFFFFFu, ad, off);
        }
        if (lane == 0) { wn[warp] = an; wd[warp] = ad; }
        __syncthreads();
        if (tid == 0) {
            double n0 = 0.0, dd0 = 0.0, n1 = 0.0, dd1 = 0.0;
            #pragma unroll
            for (int j = 0; j < 4; ++j) { n0 += wn[j]; dd0 += wd[j]; }
            #pragma unroll
            for (int j = 4; j < 8; ++j) { n1 += wn[j]; dd1 += wd[j]; }
            double acc = n0 / (dd0 + 1e-5) + n1 / (dd1 + 1e-5);
            out[0] = (float)(acc / (double)BB);
            g_count = 0;   // reset for next graph replay
        }
    }
}

extern "C" void kernel_launch(void* const* d_in, const int* in_sizes, int n_in,
                              void* d_out, int out_size) {
    const float* pred = (const float*)d_in[0];
    const float* tgt  = (const float*)d_in[1];
    (void)in_sizes; (void)n_in; (void)out_size;

    k_passBC<<<NPLANE * 3, 256>>>(tgt);             // 384 blocks
    k_pass3<<<NBLK3, 256>>>(pred, (float*)d_out);   // 1152 blocks
}

// round 10
// speedup vs baseline: 1.0904x; 1.0803x over previous
#include <cuda_runtime.h>
#include <math.h>

#define BB 2
#define DD 64
#define HH 96
#define WW 96
#define VOL (DD*HH*WW)          // 589824
#define NVOX (BB*VOL)           // 1179648
#define HWSZ (HH*WW)            // 9216
#define NPLANE (BB*DD)          // 128
#define WT 32                   // passBC w-tile
#define HT 24                   // passBC h-tile (4 per plane)
#define WT3 16                  // pass3 w-tile
#define CLAMP 25.0f

#define NBLKBC (NPLANE*3*4)     // 1536 passBC blocks
#define NBLK3 (BB*HH*(WW/WT3))  // 1152 pass3 blocks

// Scratch (device globals: allocation-free per harness rules)
__device__ float g_x[NVOX];               // packed bp-bn after W+H transform (clamped 25)
__device__ volatile float g_pn[NBLK3];
__device__ volatile float g_pd[NBLK3];
__device__ unsigned g_count;              // zero-init; last block resets -> deterministic

// Windowed nearest-set-bit distance: 96-bit local window {m0,m1,m2} covering
// [w0-32, w0+64); voxel at bit wl of m1. Clamp usage guarantees d<=5 matters,
// always within the window.
__device__ __forceinline__ int win_dist(unsigned m0, unsigned m1, unsigned m2, int wl) {
    unsigned long long U = (unsigned long long)m1 | ((unsigned long long)m2 << 32);
    unsigned long long D = (unsigned long long)m0 | ((unsigned long long)m1 << 32);
    unsigned long long a = U >> wl;           // bit0 = self, upward
    unsigned long long b = D << (31 - wl);    // MSB = self, downward
    int up = a ? (__ffsll((long long)a) - 1) : 64;
    int dn = b ? __clzll((long long)b) : 64;
    return (up < dn) ? up : dn;
}

// Fused: windowed mask build + pass1 (clamped W bit-scan) + pass2 (k=1..4
// branch-free H stencil). Block = (plane, h-tile of 24, w-tile of 32).
__global__ __launch_bounds__(256) void k_passBC(const float* __restrict__ tgt) {
    __shared__ unsigned sm[32][3];      // rows h0-4..h0+27, segs wt-1..wt+1
    __shared__ float s1p[32][WT];
    __shared__ float s1n[32][WT];

    int blk = blockIdx.x;
    int wt = blk % 3;
    int ht = (blk / 3) & 3;
    int bd = blk / 12;
    int base = bd * HWSZ;
    int h0 = ht * HT;
    int tid = threadIdx.x;
    int lane = tid & 31;
    int warp = tid >> 5;                // 0..7

    // Ballot masks: 96 warp-tasks (32 rows x 3 segs), 12 per warp.
    #pragma unroll
    for (int task = warp; task < 96; task += 8) {
        int r = task >> 2;              // need r in 0..31: 96 tasks = 32*3...
        r = task / 3;
        int s = task - r * 3;
        int hr = h0 - 4 + r;
        int sw = wt - 1 + s;
        unsigned m = 0;
        if (hr >= 0 && hr < HH && sw >= 0 && sw < 3) {
            float v = tgt[base + hr * WW + sw * 32 + lane];
            m = __ballot_sync(0xFFFFFFFFu, v > 0.5f);
        }
        if (lane == 0) sm[r][s] = m;
    }
    __syncthreads();

    // pass1: clamped W-distance via windowed bit scan; rows outside -> CLAMP.
    unsigned val0 = (wt > 0) ? 0xFFFFFFFFu : 0u;
    unsigned val2 = (wt < 2) ? 0xFFFFFFFFu : 0u;
    #pragma unroll
    for (int r = warp; r < 32; r += 8) {
        int hr = h0 - 4 + r;
        float vp, vn;
        if (hr < 0 || hr >= HH) {
            vp = CLAMP; vn = CLAMP;
        } else {
            unsigned m0 = sm[r][0], m1 = sm[r][1], m2 = sm[r][2];
            int dn = win_dist(m0, m1, m2, lane);                       // nearest 1
            int dp = win_dist(val0 & ~m0, ~m1, val2 & ~m2, lane);      // nearest 0
            vp = (dp >= 5) ? CLAMP : (float)(dp * dp);
            vn = (dn >= 5) ? CLAMP : (float)(dn * dn);
        }
        s1p[r][lane] = vp;
        s1n[r][lane] = vn;
    }
    __syncthreads();

    // pass2 along H: fixed k=1..4 stencil (k=5 -> 25 >= clamp), rows 4..27.
    #pragma unroll
    for (int r4 = warp; r4 < HT; r4 += 8) {
        int r = r4 + 4;
        float bp = s1p[r][lane];
        float bn = s1n[r][lane];
        #pragma unroll
        for (int k = 1; k <= 4; ++k) {
            float k2 = (float)(k * k);
            bp = fminf(bp, s1p[r - k][lane] + k2);
            bp = fminf(bp, s1p[r + k][lane] + k2);
            bn = fminf(bn, s1n[r - k][lane] + k2);
            bn = fminf(bn, s1n[r + k][lane] + k2);
        }
        // Exactly one of bp,bn is 0 -> pack as signed value.
        g_x[base + (h0 + r4) * WW + wt * WT + lane] = bp - bn;
    }
}

// Pass3: k=1..4 D-stencil with 4-consecutive-i register reuse, fused loss
// epilogue (group-4 log) + grid-final reduction.
__global__ __launch_bounds__(256) void k_pass3(const float* __restrict__ pred,
                                               float* __restrict__ out) {
    __shared__ float sfp[DD + 8][17];   // stride 17: no bank conflicts
    __shared__ float sfn[DD + 8][17];
    __shared__ float rnm[8], rdm[8];
    __shared__ int s_last;

    int wt = blockIdx.x % (WW / WT3);       // 0..5
    int bh = blockIdx.x / (WW / WT3);
    int b = bh / HH;
    int h = bh % HH;
    int base = b * VOL + h * WW + wt * WT3;
    int tid = threadIdx.x;
    int w = tid & 15;
    int c0 = tid >> 4;                      // 0..15
    int i0 = c0 * 4;                        // 4 consecutive i per thread

    // Issue pred LDGs first (latency hidden behind smem fill + stencil).
    float pv[4];
    #pragma unroll
    for (int j = 0; j < 4; ++j) pv[j] = pred[base + (i0 + j) * HWSZ + w];

    // Pad rows [0..3] and [DD+4..DD+7].
    if (tid < 128) {
        int r = tid >> 4;
        int ww_ = tid & 15;
        int row = (r < 4) ? r : (DD + r);
        sfp[row][ww_] = CLAMP;
        sfn[row][ww_] = CLAMP;
    }
    // Load + decode packed values (coalesced 64B per 16 lanes).
    #pragma unroll
    for (int r = tid; r < DD * WT3; r += 256) {
        int d = r >> 4, ww_ = r & 15;
        float x = g_x[base + d * HWSZ + ww_];
        sfp[4 + d][ww_] = fmaxf(x, 0.0f);
        sfn[4 + d][ww_] = fmaxf(-x, 0.0f);
    }
    __syncthreads();

    // Pull the 12 needed rows into registers (shared across 4 voxels).
    float rp[12], rn_[12];
    #pragma unroll
    for (int j = 0; j < 12; ++j) {
        rp[j]  = sfp[i0 + j][w];    // covers padded rows i0 .. i0+11
        rn_[j] = sfn[i0 + j][w];
    }

    float mArr[4], pcArr[4];
    #pragma unroll
    for (int j = 0; j < 4; ++j) {
        float bp = rp[j + 4];
        float bn = rn_[j + 4];
        #pragma unroll
        for (int k = 1; k <= 4; ++k) {
            float k2 = (float)(k * k);
            bp = fminf(bp, rp[j + 4 - k] + k2);
            bp = fminf(bp, rp[j + 4 + k] + k2);
            bn = fminf(bn, rn_[j + 4 - k] + k2);
            bn = fminf(bn, rn_[j + 4 + k] + k2);
        }
        mArr[j] = fmaxf(bp, bn);                    // exactly one is 0
        pcArr[j] = (bp > 0.0f) ? pv[j] : (1.0f - pv[j]);   // t==1 <=> bp>0
    }

    float accn, accd;
    bool fast = true;
    float prod = 1.0f;
    #pragma unroll
    for (int j = 0; j < 4; ++j) {
        if (mArr[j] > 9.0f) fast = false;
        prod *= pcArr[j];
    }
    if (fast && prod > 1e-30f) {
        accn = -__logf(prod);      // all w==1: sum(-log pc) == -log(prod)
        accd = 4.0f;
    } else {
        accn = 0.0f; accd = 0.0f;
        #pragma unroll
        for (int j = 0; j < 4; ++j) {
            float m = mArr[j];
            float wgt;
            if (m <= 9.0f)       wgt = 1.0f;
            else if (m >= 25.0f) wgt = 0.0f;
            else                 wgt = 1.0f - (sqrtf(m) - 3.0f) * 0.5f;
            float bce = -fmaxf(__logf(pcArr[j]), -100.0f);
            accn += bce * wgt;
            accd += wgt;
        }
    }

    #pragma unroll
    for (int off = 16; off > 0; off >>= 1) {
        accn += __shfl_down_sync(0xFFFFFFFFu, accn, off);
        accd += __shfl_down_sync(0xFFFFFFFFu, accd, off);
    }
    int warp = tid >> 5, lane = tid & 31;
    if (lane == 0) { rnm[warp] = accn; rdm[warp] = accd; }
    __syncthreads();
    if (tid == 0) {
        float sn = 0.0f, sd = 0.0f;
        #pragma unroll
        for (int j = 0; j < 8; ++j) { sn += rnm[j]; sd += rdm[j]; }
        g_pn[blockIdx.x] = sn;
        g_pd[blockIdx.x] = sd;
        __threadfence();
        unsigned old = atomicAdd(&g_count, 1u);
        s_last = (old == NBLK3 - 1) ? 1 : 0;
    }
    __syncthreads();

    // Last block: reduce all 1152 partials -> scalar, reset counter.
    if (s_last) {
        __shared__ double wn[8], wd[8];
        const int PER_B = NBLK3 / BB;     // 576
        int rb = tid >> 7;                // 0..1 (batch)
        int j0 = tid & 127;
        double an = 0.0, ad = 0.0;
        #pragma unroll
        for (int j = j0; j < PER_B; j += 128) {
            an += (double)g_pn[rb * PER_B + j];
            ad += (double)g_pd[rb * PER_B + j];
        }
        #pragma unroll
        for (int off = 16; off > 0; off >>= 1) {
            an += __shfl_down_sync(0xFFFFFFFFu, an, off);
            ad += __shfl_down_sync(0xFFFFFFFFu, ad, off);
        }
        if (lane == 0) { wn[warp] = an; wd[warp] = ad; }
        __syncthreads();
        if (tid == 0) {
            double n0 = 0.0, dd0 = 0.0, n1 = 0.0, dd1 = 0.0;
            #pragma unroll
            for (int j = 0; j < 4; ++j) { n0 += wn[j]; dd0 += wd[j]; }
            #pragma unroll
            for (int j = 4; j < 8; ++j) { n1 += wn[j]; dd1 += wd[j]; }
            double acc = n0 / (dd0 + 1e-5) + n1 / (dd1 + 1e-5);
            out[0] = (float)(acc / (double)BB);
            g_count = 0;   // reset for next graph replay
        }
    }
}

extern "C" void kernel_launch(void* const* d_in, const int* in_sizes, int n_in,
                              void* d_out, int out_size) {
    const float* pred = (const float*)d_in[0];
    const float* tgt  = (const float*)d_in[1];
    (void)in_sizes; (void)n_in; (void)out_size;

    k_passBC<<<NBLKBC, 256>>>(tgt);                 // 1536 blocks
    k_pass3<<<NBLK3, 256>>>(pred, (float*)d_out);   // 1152 blocks
}